// round 14
// baseline (speedup 1.0000x reference)
#include <cuda_runtime.h>
#include <cuda_bf16.h>
#include <cstdint>
#include <math.h>

#define B_   64
#define T_   512
#define I_   256
#define H_   1024
#define F_   11
#define BT   (B_ * T_)
#define G4   (4 * H_)

#define OUT_STATE_OFF  0
#define OUT_REWARD_OFF (BT * F_)
#define OUT_HT_OFF     (OUT_REWARD_OFF + BT)
#define OUT_CT_OFF     (OUT_HT_OFF + B_ * H_)

// ---------------- scratch globals ----------------
__device__ float g_Z[BT * G4];
__device__ float g_sh[BT * H_];
__device__ float g_proj[BT * 16];
__device__ __align__(16) __nv_bfloat16 g_x_hi[BT * I_],  g_x_lo[BT * I_];
__device__ __align__(16) __nv_bfloat16 g_r_hi[BT * H_],  g_r_lo[BT * H_];
__device__ __align__(16) __nv_bfloat16 g_wih_hi[G4 * I_], g_wih_lo[G4 * I_];
__device__ __align__(16) __nv_bfloat16 g_whh_hi[G4 * H_], g_whh_lo[G4 * H_];
__device__ __align__(16) __nv_bfloat16 g_wsh_hi[H_ * H_], g_wsh_lo[H_ * H_];
// 4-deep h ring: WAR guard gets 2 steps of slack (no per-step grid rendezvous)
__device__ __align__(16) __nv_bfloat16 g_hb_hi[4][B_ * H_], g_hb_lo[4][B_ * H_];
// dataflow flags
__device__ int g_prod[T_ + 1][8];
__device__ int g_cons[T_];

// ---------------- helpers ----------------
__device__ __forceinline__ uint32_t smem_u32(const void* p) {
    uint32_t a;
    asm("{ .reg .u64 t; cvta.to.shared.u64 t, %1; cvt.u32.u64 %0, t; }" : "=r"(a) : "l"(p));
    return a;
}
__device__ __forceinline__ void ldmx4(uint32_t* r, uint32_t addr) {
    asm volatile("ldmatrix.sync.aligned.m8n8.x4.shared.b16 {%0,%1,%2,%3}, [%4];"
        : "=r"(r[0]), "=r"(r[1]), "=r"(r[2]), "=r"(r[3]) : "r"(addr));
}
__device__ __forceinline__ void mma_bf16(float* d, const uint32_t* a, uint32_t b0, uint32_t b1) {
    asm volatile("mma.sync.aligned.m16n8k16.row.col.f32.bf16.bf16.f32 "
        "{%0,%1,%2,%3}, {%4,%5,%6,%7}, {%8,%9}, {%0,%1,%2,%3};"
        : "+f"(d[0]), "+f"(d[1]), "+f"(d[2]), "+f"(d[3])
        : "r"(a[0]), "r"(a[1]), "r"(a[2]), "r"(a[3]), "r"(b0), "r"(b1));
}
__device__ __forceinline__ void cp16(uint32_t dst, const void* src) {
    asm volatile("cp.async.cg.shared.global [%0], [%1], 16;" :: "r"(dst), "l"(src));
}
__device__ __forceinline__ void cp_commit() { asm volatile("cp.async.commit_group;" ::: "memory"); }
__device__ __forceinline__ void cp_wait1()  { asm volatile("cp.async.wait_group 1;" ::: "memory"); }
__device__ __forceinline__ void cp_wait0()  { asm volatile("cp.async.wait_group 0;" ::: "memory"); }

// ---- FMA-pipe transcendentals (kept: neutral perf, good accuracy) ----
__device__ __forceinline__ float exp_fast(float x) {
    x = fminf(fmaxf(x, -30.f), 30.f);
    const float y = x * 1.4426950408889634f;
    const float R = y + 12582912.f;
    const float f = y - (R - 12582912.f);
    float p =               1.5403530e-4f;
    p = fmaf(p, f, 1.3333558e-3f);
    p = fmaf(p, f, 9.6181291e-3f);
    p = fmaf(p, f, 5.5504109e-2f);
    p = fmaf(p, f, 2.4022651e-1f);
    p = fmaf(p, f, 6.9314718e-1f);
    p = fmaf(p, f, 1.0f);
    return __int_as_float(__float_as_int(p) + (__float_as_int(R) << 23));
}
__device__ __forceinline__ float rcp_fast(float d) {
    float x = __int_as_float(0x7EF311C3 - __float_as_int(d));
    x = x * fmaf(-d, x, 2.f);
    x = x * fmaf(-d, x, 2.f);
    x = x * fmaf(-d, x, 2.f);
    return x;
}

// ---------------- flag init ----------------
__global__ void init_flags_kernel() {
    int i = blockIdx.x * blockDim.x + threadIdx.x;
    if (i < (T_ + 1) * 8) (&g_prod[0][0])[i] = (i < 8) ? 16 : 0;  // h(0) ready
    if (i < T_) g_cons[i] = 0;
}

// ---------------- fp32 -> bf16 hi/lo split ----------------
__global__ __launch_bounds__(256) void split_kernel(
    const float* __restrict__ src, __nv_bfloat16* __restrict__ hi,
    __nv_bfloat16* __restrict__ lo, int n)
{
    int i = blockIdx.x * blockDim.x + threadIdx.x;
    if (i >= n) return;
    float v = src[i];
    __nv_bfloat16 h = __float2bfloat16(v);
    hi[i] = h;
    lo[i] = __float2bfloat16(v - __bfloat162float(h));
}

// ---------------- bf16 split-precision GEMM (unchanged, passing) ----------------
#define GS_STRIDE_B 80
#define GS_ABUF     10240
#define GS_BOFF     20480
#define GS_BUF      40960
#define GEMM_SMEM   81920

__global__ __launch_bounds__(256) void hgemm_tn(
    const __nv_bfloat16* __restrict__ Ahi, const __nv_bfloat16* __restrict__ Alo,
    const __nv_bfloat16* __restrict__ Whi, const __nv_bfloat16* __restrict__ Wlo,
    const float* __restrict__ bias1, const float* __restrict__ bias2,
    float* __restrict__ C, int M, int N, int K)
{
    extern __shared__ char smg[];
    const uint32_t sb = smem_u32(smg);
    const int tid = threadIdx.x, lane = tid & 31, wid = tid >> 5;
    const int wm = wid >> 2, wn = wid & 3;
    const int m0 = blockIdx.y * 128, n0 = blockIdx.x * 128;

    float acc[4][4][4];
#pragma unroll
    for (int a = 0; a < 4; a++)
#pragma unroll
        for (int b = 0; b < 4; b++)
#pragma unroll
            for (int c = 0; c < 4; c++) acc[a][b][c] = 0.f;

    const int mrow_ld = lane & 15, kA = (lane >> 4) * 8;
    const int nrow_ld = (lane & 7) + ((lane >> 4) << 3), kB = ((lane >> 3) & 1) * 8;
    const int crow = tid >> 1, cd = tid & 1;
    const __nv_bfloat16* As = cd ? Alo : Ahi;
    const __nv_bfloat16* Bs = cd ? Wlo : Whi;
    const int nk = K / 32;

    {
        uint32_t ab = sb + cd * GS_ABUF;
        uint32_t bb = sb + GS_BOFF + cd * GS_ABUF;
#pragma unroll
        for (int s = 0; s < 4; s++) {
            cp16(ab + crow * GS_STRIDE_B + s * 16, (const char*)(As + (size_t)(m0 + crow) * K) + s * 16);
            cp16(bb + crow * GS_STRIDE_B + s * 16, (const char*)(Bs + (size_t)(n0 + crow) * K) + s * 16);
        }
        cp_commit();
    }

    for (int kk = 0; kk < nk; kk++) {
        if (kk + 1 < nk) {
            const int k0 = (kk + 1) * 32;
            uint32_t bufb = ((kk + 1) & 1) * GS_BUF;
            uint32_t ab = sb + bufb + cd * GS_ABUF;
            uint32_t bb = sb + bufb + GS_BOFF + cd * GS_ABUF;
#pragma unroll
            for (int s = 0; s < 4; s++) {
                cp16(ab + crow * GS_STRIDE_B + s * 16, (const char*)(As + (size_t)(m0 + crow) * K + k0) + s * 16);
                cp16(bb + crow * GS_STRIDE_B + s * 16, (const char*)(Bs + (size_t)(n0 + crow) * K + k0) + s * 16);
            }
            cp_commit();
            cp_wait1();
        } else {
            cp_wait0();
        }
        __syncthreads();

        const uint32_t bufb = sb + (kk & 1) * GS_BUF;
#pragma unroll
        for (int ks = 0; ks < 2; ks++) {
            uint32_t ahi[4][4], alo[4][4], bhi[2][4], blo[2][4];
#pragma unroll
            for (int mt = 0; mt < 4; mt++) {
                uint32_t ra = bufb + (wm * 64 + mt * 16 + mrow_ld) * GS_STRIDE_B + (ks * 16 + kA) * 2;
                ldmx4(ahi[mt], ra);
                ldmx4(alo[mt], ra + GS_ABUF);
            }
#pragma unroll
            for (int nb = 0; nb < 2; nb++) {
                uint32_t rb = bufb + GS_BOFF + (wn * 32 + nb * 16 + nrow_ld) * GS_STRIDE_B + (ks * 16 + kB) * 2;
                ldmx4(bhi[nb], rb);
                ldmx4(blo[nb], rb + GS_ABUF);
            }
#pragma unroll
            for (int mt = 0; mt < 4; mt++)
#pragma unroll
                for (int nt = 0; nt < 4; nt++) {
                    const int nb = nt >> 1, hf = (nt & 1) * 2;
                    mma_bf16(acc[mt][nt], ahi[mt], bhi[nb][hf], bhi[nb][hf + 1]);
                    mma_bf16(acc[mt][nt], ahi[mt], blo[nb][hf], blo[nb][hf + 1]);
                    mma_bf16(acc[mt][nt], alo[mt], bhi[nb][hf], bhi[nb][hf + 1]);
                }
        }
        __syncthreads();
    }

    const int g = lane >> 2, tq = lane & 3;
#pragma unroll
    for (int mt = 0; mt < 4; mt++)
#pragma unroll
        for (int nt = 0; nt < 4; nt++) {
            const int row = m0 + wm * 64 + mt * 16 + g;
            const int col = n0 + wn * 32 + nt * 8 + tq * 2;
            float b0 = 0.f, b1 = 0.f;
            if (bias1) { b0 += bias1[col]; b1 += bias1[col + 1]; }
            if (bias2) { b0 += bias2[col]; b1 += bias2[col + 1]; }
            C[(size_t)row * N + col]           = acc[mt][nt][0] + b0;
            C[(size_t)row * N + col + 1]       = acc[mt][nt][1] + b1;
            C[(size_t)(row + 8) * N + col]     = acc[mt][nt][2] + b0;
            C[(size_t)(row + 8) * N + col + 1] = acc[mt][nt][3] + b1;
        }
}

// ---------------- persistent HMMA LSTM recurrence (flag-pipelined, 4-deep h ring) --------
#define RNC 128
#define RS_WHI   0
#define RS_WLO   66048
#define RS_H     132096
#define RS_HBUF  34816
#define RS_HLO   17408
#define RS_ZSM   201728
#define LSTM_SMEM 210176

__global__ __launch_bounds__(256, 1) void lstm_mma_kernel(const float* __restrict__ c0,
                                                          float* __restrict__ out)
{
    extern __shared__ char sml[];
    const uint32_t sb = smem_u32(sml);
    float* zsm = reinterpret_cast<float*>(sml + RS_ZSM);

    const int tid = threadIdx.x, bid = blockIdx.x;
    const int lane = tid & 31, wid = tid >> 5;
    const int wm = wid >> 2, wn = wid & 3;
    const int j0 = bid * 8;
    const int my_chunk = bid >> 4;

#pragma unroll
    for (int u = 0; u < 16; u++) {
        const int idx = tid + u * 256;
        const int r = idx >> 7, seg = idx & 127;
        const int grow = (r >> 3) * H_ + j0 + (r & 7);
        cp16(sb + RS_WHI + r * 2064 + seg * 16, (const char*)(g_whh_hi + (size_t)grow * H_) + seg * 16);
        cp16(sb + RS_WLO + r * 2064 + seg * 16, (const char*)(g_whh_lo + (size_t)grow * H_) + seg * 16);
    }
    cp_commit(); cp_wait0(); __syncthreads();

    float creg[2];
#pragma unroll
    for (int r = 0; r < 2; r++) {
        const int e = tid + r * 256;
        creg[r] = c0[(e >> 3) * H_ + j0 + (e & 7)];
    }

    const int mrow_ld = lane & 15, kA = (lane >> 4) * 8;
    const int nrow_ld = (lane & 7) + ((lane >> 4) << 3), kB = ((lane >> 3) & 1) * 8;

    for (int t = 0; t < T_; t++) {
        const char* hhi = (const char*)g_hb_hi[t & 3];
        const char* hlo = (const char*)g_hb_lo[t & 3];

        // early z loads (DRAM latency hidden under staging+MMA)
        float zr[2][4];
#pragma unroll
        for (int r = 0; r < 2; r++) {
            const int e = tid + r * 256;
            const size_t zoff = ((size_t)((e >> 3) * T_ + t)) * G4 + j0 + (e & 7);
#pragma unroll
            for (int gg = 0; gg < 4; gg++) zr[r][gg] = g_Z[zoff + (size_t)gg * H_];
        }

        float acc[2][4] = {{0.f,0.f,0.f,0.f},{0.f,0.f,0.f,0.f}};

        {
            volatile int* f = &g_prod[t][0];
            while (*f < 16) { }
#pragma unroll
            for (int i = 0; i < 8; i++) {
                const int u = tid + i * 256, d = u >> 10, v = u & 1023;
                const int b = v >> 4, s = v & 15;
                cp16(sb + RS_H + d * RS_HLO + b * 272 + s * 16,
                     (d ? hlo : hhi) + b * 2048 + s * 16);
            }
            cp_commit();
        }

        for (int c = 0; c < 8; c++) {
            if (c + 1 < 8) {
                volatile int* f = &g_prod[t][c + 1];
                while (*f < 16) { }
                const uint32_t hb = sb + RS_H + ((c + 1) & 1) * RS_HBUF;
#pragma unroll
                for (int i = 0; i < 8; i++) {
                    const int u = tid + i * 256, d = u >> 10, v = u & 1023;
                    const int b = v >> 4, s = v & 15;
                    cp16(hb + d * RS_HLO + b * 272 + s * 16,
                         (d ? hlo : hhi) + b * 2048 + (c + 1) * 256 + s * 16);
                }
                cp_commit();
                cp_wait1();
            } else {
                cp_wait0();
                if (tid == 0) atomicAdd(&g_cons[t], 1);   // done reading h(t)
            }
            __syncthreads();

            const uint32_t hb = sb + RS_H + (c & 1) * RS_HBUF;
#pragma unroll
            for (int ks = 0; ks < 8; ks++) {
                uint32_t ahr[4], alr[4], bhr[4], blr[4];
                const uint32_t ra = sb + RS_WHI + (wm * 16 + mrow_ld) * 2064 + (c * 128 + ks * 16 + kA) * 2;
                ldmx4(ahr, ra);
                ldmx4(alr, ra + (RS_WLO - RS_WHI));
                const uint32_t rb = hb + (wn * 16 + nrow_ld) * 272 + (ks * 16 + kB) * 2;
                ldmx4(bhr, rb);
                ldmx4(blr, rb + RS_HLO);
#pragma unroll
                for (int ti = 0; ti < 2; ti++) {
                    mma_bf16(acc[ti], ahr, bhr[ti * 2], bhr[ti * 2 + 1]);
                    mma_bf16(acc[ti], ahr, blr[ti * 2], blr[ti * 2 + 1]);
                    mma_bf16(acc[ti], alr, bhr[ti * 2], bhr[ti * 2 + 1]);
                }
            }
            __syncthreads();
        }

        {
            const int g = lane >> 2, tq = lane & 3;
#pragma unroll
            for (int ti = 0; ti < 2; ti++) {
                const int col = wn * 16 + ti * 8 + tq * 2;
                zsm[(wm * 16 + g) * 66 + col]         = acc[ti][0];
                zsm[(wm * 16 + g) * 66 + col + 1]     = acc[ti][1];
                zsm[(wm * 16 + g + 8) * 66 + col]     = acc[ti][2];
                zsm[(wm * 16 + g + 8) * 66 + col + 1] = acc[ti][3];
            }
        }
        __syncthreads();

        // WAR guard with 2 steps of slack: h(t+1) reuses the buffer that held
        // h(t-3); wait until all CTAs consumed h(t-3). Usually already true.
        if (t >= 3) {
            volatile int* f = &g_cons[t - 3];
            while (*f < RNC) { }
        }

        // gates (FMA-pipe math)
        __nv_bfloat16* __restrict__ dsthi = g_hb_hi[(t + 1) & 3];
        __nv_bfloat16* __restrict__ dstlo = g_hb_lo[(t + 1) & 3];
#pragma unroll
        for (int r = 0; r < 2; r++) {
            const int e = tid + r * 256;
            const int b = e >> 3, jj = e & 7;
            const float zi = zsm[(0 * 8 + jj) * 66 + b] + zr[r][0];
            const float zf = zsm[(1 * 8 + jj) * 66 + b] + zr[r][1];
            const float zg = zsm[(2 * 8 + jj) * 66 + b] + zr[r][2];
            const float zo = zsm[(3 * 8 + jj) * 66 + b] + zr[r][3];

            const float ef = exp_fast(-zf);
            const float ei = exp_fast(-zi);
            const float eg = exp_fast(-2.f * zg);
            const float eo = exp_fast(-zo);
            const float cc = creg[r] * rcp_fast(1.f + ef)
                           + (1.f - eg) * rcp_fast((1.f + ei) * (1.f + eg));
            const float ec = exp_fast(2.f * cc);
            const float hh = (ec - 1.f) * rcp_fast((1.f + eo) * (ec + 1.f));
            creg[r] = cc;

            const __nv_bfloat16 hi = __float2bfloat16(hh);
            const __nv_bfloat16 lo = __float2bfloat16(hh - __bfloat162float(hi));
            const int hidx = b * H_ + j0 + jj;
            dsthi[hidx] = hi; dstlo[hidx] = lo;
            const size_t ridx = ((size_t)(b * T_ + t)) * H_ + j0 + jj;
            g_r_hi[ridx] = hi; g_r_lo[ridx] = lo;
            if (t == T_ - 1) {
                out[OUT_HT_OFF + hidx] = hh;
                out[OUT_CT_OFF + hidx] = cc;
            }
        }
        __threadfence();
        __syncthreads();
        if (tid == 0) atomicAdd(&g_prod[t + 1][my_chunk], 1);
    }
}

// ---------------- heads: 14 dots per row of g_sh ----------------
__global__ __launch_bounds__(256) void heads_kernel(
    const float* __restrict__ w_att_s, const float* __restrict__ w_att_r,
    const float* __restrict__ W_state, const float* __restrict__ W_reward)
{
    const int warp = (blockIdx.x * blockDim.x + threadIdx.x) >> 5;
    const int lane = threadIdx.x & 31;
    if (warp >= BT) return;
    const float* rowp = g_sh + (size_t)warp * H_;

    float4 f[8];
#pragma unroll
    for (int i = 0; i < 8; i++)
        f[i] = *reinterpret_cast<const float4*>(rowp + lane * 32 + i * 4);

    float out[14];
#pragma unroll
    for (int fi = 0; fi < 14; fi++) {
        const float* wv = (fi == 0) ? w_att_s
                        : (fi == 1) ? w_att_r
                        : (fi < 13) ? (W_state + (fi - 2) * H_)
                        : W_reward;
        float s = 0.f;
#pragma unroll
        for (int i = 0; i < 8; i++) {
            const float4 w = *reinterpret_cast<const float4*>(wv + lane * 32 + i * 4);
            s += f[i].x * w.x + f[i].y * w.y + f[i].z * w.z + f[i].w * w.w;
        }
#pragma unroll
        for (int o = 16; o; o >>= 1) s += __shfl_xor_sync(0xffffffffu, s, o);
        out[fi] = s;
    }
    if (lane == 0) {
#pragma unroll
        for (int fi = 0; fi < 14; fi++)
            g_proj[(size_t)warp * 16 + fi] = out[fi];
    }
}

// ---------------- causal prefix-softmax scan ----------------
__global__ void scan_kernel(const float* __restrict__ b_state,
                            const float* __restrict__ b_reward,
                            float* __restrict__ out)
{
    const int b = blockIdx.x;
    const int w = threadIdx.x >> 5, lane = threadIdx.x & 31;
    const float* pbase = g_proj + (size_t)b * T_ * 16;

    if (w == 0) {
        float num = 0.f, den = 0.f, m = -INFINITY;
        const float bs = (lane < F_) ? b_state[lane] : 0.f;
        for (int t = 0; t < T_; t++) {
            const float* p = pbase + t * 16;
            const float l = p[0];
            const float v = (lane < F_) ? p[2 + lane] : 0.f;
            const float nm = fmaxf(m, l);
            const float sc = __expf(m - nm);
            const float e  = __expf(l - nm);
            den = den * sc + e;
            num = num * sc + e * v;
            m = nm;
            if (lane < F_)
                out[OUT_STATE_OFF + (size_t)(b * T_ + t) * F_ + lane] = num / den + bs;
        }
    } else if (w == 1) {
        float num = 0.f, den = 0.f, m = -INFINITY;
        const float br = b_reward[0];
        for (int t = 0; t < T_; t++) {
            const float* p = pbase + t * 16;
            const float l = p[1];
            const float v = p[13];
            const float nm = fmaxf(m, l);
            const float sc = __expf(m - nm);
            const float e  = __expf(l - nm);
            den = den * sc + e;
            num = num * sc + e * v;
            m = nm;
            if (lane == 0)
                out[OUT_REWARD_OFF + b * T_ + t] = num / den + br;
        }
    }
}

// ---------------- launch ----------------
extern "C" void kernel_launch(void* const* d_in, const int* in_sizes, int n_in,
                              void* d_out, int out_size)
{
    const float* x        = (const float*)d_in[0];
    const float* h0       = (const float*)d_in[2];
    const float* c0       = (const float*)d_in[3];
    const float* W_ih     = (const float*)d_in[4];
    const float* W_hh     = (const float*)d_in[5];
    const float* b_ih     = (const float*)d_in[6];
    const float* b_hh     = (const float*)d_in[7];
    const float* W_sh     = (const float*)d_in[8];
    const float* b_sh     = (const float*)d_in[9];
    const float* w_att_s  = (const float*)d_in[10];
    const float* w_att_r  = (const float*)d_in[12];
    const float* W_state  = (const float*)d_in[14];
    const float* b_state  = (const float*)d_in[15];
    const float* W_reward = (const float*)d_in[16];
    const float* b_reward = (const float*)d_in[17];
    float* out = (float*)d_out;

    float *Z, *sh;
    __nv_bfloat16 *xh, *xl, *rh, *rl, *wihh, *wihl, *whhh, *whhl, *wshh, *wshl, *hbh, *hbl;
    cudaGetSymbolAddress((void**)&Z,    g_Z);
    cudaGetSymbolAddress((void**)&sh,   g_sh);
    cudaGetSymbolAddress((void**)&xh,   g_x_hi);   cudaGetSymbolAddress((void**)&xl,   g_x_lo);
    cudaGetSymbolAddress((void**)&rh,   g_r_hi);   cudaGetSymbolAddress((void**)&rl,   g_r_lo);
    cudaGetSymbolAddress((void**)&wihh, g_wih_hi); cudaGetSymbolAddress((void**)&wihl, g_wih_lo);
    cudaGetSymbolAddress((void**)&whhh, g_whh_hi); cudaGetSymbolAddress((void**)&whhl, g_whh_lo);
    cudaGetSymbolAddress((void**)&wshh, g_wsh_hi); cudaGetSymbolAddress((void**)&wshl, g_wsh_lo);
    cudaGetSymbolAddress((void**)&hbh,  g_hb_hi);  cudaGetSymbolAddress((void**)&hbl,  g_hb_lo);

    cudaFuncSetAttribute(hgemm_tn, cudaFuncAttributeMaxDynamicSharedMemorySize, GEMM_SMEM);
    cudaFuncSetAttribute(lstm_mma_kernel, cudaFuncAttributeMaxDynamicSharedMemorySize, LSTM_SMEM);

    // splits + flag init
    split_kernel<<<(BT * I_) / 256, 256>>>(x, xh, xl, BT * I_);
    split_kernel<<<(G4 * I_) / 256, 256>>>(W_ih, wihh, wihl, G4 * I_);
    split_kernel<<<(G4 * H_) / 256, 256>>>(W_hh, whhh, whhl, G4 * H_);
    split_kernel<<<(H_ * H_) / 256, 256>>>(W_sh, wshh, wshl, H_ * H_);
    split_kernel<<<(B_ * H_) / 256, 256>>>(h0, hbh, hbl, B_ * H_);   // -> g_hb_*[0]
    init_flags_kernel<<<17, 256>>>();

    // Z = x @ W_ih^T + (b_ih + b_hh)
    hgemm_tn<<<dim3(G4 / 128, BT / 128), 256, GEMM_SMEM>>>(
        xh, xl, wihh, wihl, b_ih, b_hh, Z, BT, G4, I_);

    // LSTM recurrence (HMMA, dataflow-pipelined, 4-deep h ring)
    lstm_mma_kernel<<<RNC, 256, LSTM_SMEM>>>(c0, out);

    // shared = r @ W_sh^T + b_sh
    hgemm_tn<<<dim3(H_ / 128, BT / 128), 256, GEMM_SMEM>>>(
        rh, rl, wshh, wshl, b_sh, nullptr, sh, BT, H_, H_);

    // heads + scans
    heads_kernel<<<BT / 8, 256>>>(w_att_s, w_att_r, W_state, W_reward);
    scan_kernel<<<B_, 64>>>(b_state, b_reward, out);
}

// round 15
// speedup vs baseline: 1.3524x; 1.3524x over previous
#include <cuda_runtime.h>
#include <cuda_fp16.h>
#include <cstdint>
#include <math.h>

#define B_   64
#define T_   512
#define I_   256
#define H_   1024
#define F_   11
#define BT   (B_ * T_)
#define G4   (4 * H_)

#define OUT_STATE_OFF  0
#define OUT_REWARD_OFF (BT * F_)
#define OUT_HT_OFF     (OUT_REWARD_OFF + BT)
#define OUT_CT_OFF     (OUT_HT_OFF + B_ * H_)

// ---------------- scratch globals ----------------
__device__ float g_Z[BT * G4];
__device__ float g_sh[BT * H_];
__device__ float g_proj[BT * 16];
__device__ __align__(16) __half g_xf[BT * I_];
__device__ __align__(16) __half g_rf[BT * H_];
__device__ __align__(16) __half g_wih_hi[G4 * I_], g_wih_lo[G4 * I_];
__device__ __align__(16) __half g_whh_hi[G4 * H_], g_whh_lo[G4 * H_];
__device__ __align__(16) __half g_wsh_hi[H_ * H_], g_wsh_lo[H_ * H_];
__device__ __align__(16) __half g_hf[4][B_ * H_];   // 4-deep h ring (single fp16)
// dataflow flags
__device__ int g_prod[T_ + 1][8];
__device__ int g_cons[T_];

// ---------------- helpers ----------------
__device__ __forceinline__ uint32_t smem_u32(const void* p) {
    uint32_t a;
    asm("{ .reg .u64 t; cvta.to.shared.u64 t, %1; cvt.u32.u64 %0, t; }" : "=r"(a) : "l"(p));
    return a;
}
__device__ __forceinline__ void ldmx4(uint32_t* r, uint32_t addr) {
    asm volatile("ldmatrix.sync.aligned.m8n8.x4.shared.b16 {%0,%1,%2,%3}, [%4];"
        : "=r"(r[0]), "=r"(r[1]), "=r"(r[2]), "=r"(r[3]) : "r"(addr));
}
__device__ __forceinline__ void mma_f16(float* d, const uint32_t* a, uint32_t b0, uint32_t b1) {
    asm volatile("mma.sync.aligned.m16n8k16.row.col.f32.f16.f16.f32 "
        "{%0,%1,%2,%3}, {%4,%5,%6,%7}, {%8,%9}, {%0,%1,%2,%3};"
        : "+f"(d[0]), "+f"(d[1]), "+f"(d[2]), "+f"(d[3])
        : "r"(a[0]), "r"(a[1]), "r"(a[2]), "r"(a[3]), "r"(b0), "r"(b1));
}
__device__ __forceinline__ void cp16(uint32_t dst, const void* src) {
    asm volatile("cp.async.cg.shared.global [%0], [%1], 16;" :: "r"(dst), "l"(src));
}
__device__ __forceinline__ void cp_commit() { asm volatile("cp.async.commit_group;" ::: "memory"); }
__device__ __forceinline__ void cp_wait2()  { asm volatile("cp.async.wait_group 2;" ::: "memory"); }
__device__ __forceinline__ void cp_wait1()  { asm volatile("cp.async.wait_group 1;" ::: "memory"); }
__device__ __forceinline__ void cp_wait0()  { asm volatile("cp.async.wait_group 0;" ::: "memory"); }

// ---- FMA-pipe transcendentals ----
__device__ __forceinline__ float exp_fast(float x) {
    x = fminf(fmaxf(x, -30.f), 30.f);
    const float y = x * 1.4426950408889634f;
    const float R = y + 12582912.f;
    const float f = y - (R - 12582912.f);
    float p =               1.5403530e-4f;
    p = fmaf(p, f, 1.3333558e-3f);
    p = fmaf(p, f, 9.6181291e-3f);
    p = fmaf(p, f, 5.5504109e-2f);
    p = fmaf(p, f, 2.4022651e-1f);
    p = fmaf(p, f, 6.9314718e-1f);
    p = fmaf(p, f, 1.0f);
    return __int_as_float(__float_as_int(p) + (__float_as_int(R) << 23));
}
__device__ __forceinline__ float rcp_fast(float d) {
    float x = __int_as_float(0x7EF311C3 - __float_as_int(d));
    x = x * fmaf(-d, x, 2.f);
    x = x * fmaf(-d, x, 2.f);
    x = x * fmaf(-d, x, 2.f);
    return x;
}

// ---------------- init / conversion kernels ----------------
__global__ void init_flags_kernel() {
    int i = blockIdx.x * blockDim.x + threadIdx.x;
    if (i < (T_ + 1) * 8) (&g_prod[0][0])[i] = (i < 8) ? 16 : 0;  // h(0) ready
    if (i < T_) g_cons[i] = 0;
}
__global__ __launch_bounds__(256) void cvt16_kernel(
    const float* __restrict__ src, __half* __restrict__ dst, int n)
{
    int i = blockIdx.x * blockDim.x + threadIdx.x;
    if (i < n) dst[i] = __float2half(src[i]);
}
__global__ __launch_bounds__(256) void split16_kernel(
    const float* __restrict__ src, __half* __restrict__ hi,
    __half* __restrict__ lo, int n)
{
    int i = blockIdx.x * blockDim.x + threadIdx.x;
    if (i >= n) return;
    float v = src[i];
    __half h = __float2half(v);
    hi[i] = h;
    lo[i] = __float2half(v - __half2float(h));
}

// ---------------- fp16 2-term GEMM: C = A(f16) @ (Whi+Wlo)(f16)^T + biases --------
// 128x128 tile, BK=32, 256 threads, 8 warps (2m x 4n).
#define G2_A    0
#define G2_WH   10240
#define G2_WL   20480
#define G2_BUF  30720
#define GEMM_SMEM 61440

__global__ __launch_bounds__(256) void hgemm2(
    const __half* __restrict__ A,
    const __half* __restrict__ Whi, const __half* __restrict__ Wlo,
    const float* __restrict__ bias1, const float* __restrict__ bias2,
    float* __restrict__ C, int M, int N, int K)
{
    extern __shared__ char smg[];
    const uint32_t sb = smem_u32(smg);
    const int tid = threadIdx.x, lane = tid & 31, wid = tid >> 5;
    const int wm = wid >> 2, wn = wid & 3;
    const int m0 = blockIdx.y * 128, n0 = blockIdx.x * 128;

    float acc[4][4][4];
#pragma unroll
    for (int a = 0; a < 4; a++)
#pragma unroll
        for (int b = 0; b < 4; b++)
#pragma unroll
            for (int c = 0; c < 4; c++) acc[a][b][c] = 0.f;

    const int mrow_ld = lane & 15, kA = (lane >> 4) * 8;
    const int nrow_ld = (lane & 7) + ((lane >> 4) << 3), kB = ((lane >> 3) & 1) * 8;
    const int nk = K / 32;

    // stage: per buffer, 3 tiles x 128 rows x 4 segs(16B); 2 segs per tile per thread
    {
        uint32_t bu = sb;
#pragma unroll
        for (int i = 0; i < 2; i++) {
            const int u = tid + i * 256, row = u >> 2, s = u & 3;
            cp16(bu + G2_A  + row * 80 + s * 16, (const char*)(A   + (size_t)(m0 + row) * K) + s * 16);
            cp16(bu + G2_WH + row * 80 + s * 16, (const char*)(Whi + (size_t)(n0 + row) * K) + s * 16);
            cp16(bu + G2_WL + row * 80 + s * 16, (const char*)(Wlo + (size_t)(n0 + row) * K) + s * 16);
        }
        cp_commit();
    }

    for (int kk = 0; kk < nk; kk++) {
        if (kk + 1 < nk) {
            const int k0 = (kk + 1) * 32;
            uint32_t bu = sb + ((kk + 1) & 1) * G2_BUF;
#pragma unroll
            for (int i = 0; i < 2; i++) {
                const int u = tid + i * 256, row = u >> 2, s = u & 3;
                cp16(bu + G2_A  + row * 80 + s * 16, (const char*)(A   + (size_t)(m0 + row) * K + k0) + s * 16);
                cp16(bu + G2_WH + row * 80 + s * 16, (const char*)(Whi + (size_t)(n0 + row) * K + k0) + s * 16);
                cp16(bu + G2_WL + row * 80 + s * 16, (const char*)(Wlo + (size_t)(n0 + row) * K + k0) + s * 16);
            }
            cp_commit();
            cp_wait1();
        } else {
            cp_wait0();
        }
        __syncthreads();

        const uint32_t bu = sb + (kk & 1) * G2_BUF;
#pragma unroll
        for (int ks = 0; ks < 2; ks++) {
            uint32_t af[4][4], bh[2][4], bl[2][4];
#pragma unroll
            for (int mt = 0; mt < 4; mt++)
                ldmx4(af[mt], bu + G2_A + (wm * 64 + mt * 16 + mrow_ld) * 80 + (ks * 16 + kA) * 2);
#pragma unroll
            for (int nb = 0; nb < 2; nb++) {
                uint32_t rb = bu + G2_WH + (wn * 32 + nb * 16 + nrow_ld) * 80 + (ks * 16 + kB) * 2;
                ldmx4(bh[nb], rb);
                ldmx4(bl[nb], rb + (G2_WL - G2_WH));
            }
#pragma unroll
            for (int mt = 0; mt < 4; mt++)
#pragma unroll
                for (int nt = 0; nt < 4; nt++) {
                    const int nb = nt >> 1, hf = (nt & 1) * 2;
                    mma_f16(acc[mt][nt], af[mt], bh[nb][hf], bh[nb][hf + 1]);
                    mma_f16(acc[mt][nt], af[mt], bl[nb][hf], bl[nb][hf + 1]);
                }
        }
        __syncthreads();
    }

    const int g = lane >> 2, tq = lane & 3;
#pragma unroll
    for (int mt = 0; mt < 4; mt++)
#pragma unroll
        for (int nt = 0; nt < 4; nt++) {
            const int row = m0 + wm * 64 + mt * 16 + g;
            const int col = n0 + wn * 32 + nt * 8 + tq * 2;
            float b0 = 0.f, b1 = 0.f;
            if (bias1) { b0 += bias1[col]; b1 += bias1[col + 1]; }
            if (bias2) { b0 += bias2[col]; b1 += bias2[col + 1]; }
            C[(size_t)row * N + col]           = acc[mt][nt][0] + b0;
            C[(size_t)row * N + col + 1]       = acc[mt][nt][1] + b1;
            C[(size_t)(row + 8) * N + col]     = acc[mt][nt][2] + b0;
            C[(size_t)(row + 8) * N + col + 1] = acc[mt][nt][3] + b1;
        }
}

// ---------------- persistent LSTM recurrence (fp16, 2-term, 4-chunk ring) ----------
// 128 CTAs x 256 threads. CTA bid owns gate rows {g*1024 + bid*8 + jj}.
// W slice fp16 hi/lo resident; h single fp16 streamed in 8 K-chunks of 128.
#define RNC 128
#define RS_WHI   0
#define RS_WLO   66048          // 32 rows * 2064B each dtype
#define RS_H     132096         // 4 bufs * 17408 (64 rows * 272B)
#define RS_HBUF  17408
#define RS_ZSM   201728         // 32*66*4 = 8448
#define LSTM_SMEM 210176

__global__ __launch_bounds__(256, 1) void lstm_mma_kernel(const float* __restrict__ c0,
                                                          float* __restrict__ out)
{
    extern __shared__ char sml[];
    const uint32_t sb = smem_u32(sml);
    float* zsm = reinterpret_cast<float*>(sml + RS_ZSM);

    const int tid = threadIdx.x, bid = blockIdx.x;
    const int lane = tid & 31, wid = tid >> 5;
    const int wm = wid >> 2, wn = wid & 3;
    const int j0 = bid * 8;
    const int my_chunk = bid >> 4;

    // one-time: W slice (32 rows x 1024 fp16) hi+lo into smem (4096 segs each)
#pragma unroll
    for (int u = 0; u < 16; u++) {
        const int idx = tid + u * 256;
        const int r = idx >> 7, seg = idx & 127;
        const int grow = (r >> 3) * H_ + j0 + (r & 7);
        cp16(sb + RS_WHI + r * 2064 + seg * 16, (const char*)(g_whh_hi + (size_t)grow * H_) + seg * 16);
        cp16(sb + RS_WLO + r * 2064 + seg * 16, (const char*)(g_whh_lo + (size_t)grow * H_) + seg * 16);
    }
    cp_commit(); cp_wait0(); __syncthreads();

    float creg[2];
#pragma unroll
    for (int r = 0; r < 2; r++) {
        const int e = tid + r * 256;
        creg[r] = c0[(e >> 3) * H_ + j0 + (e & 7)];
    }

    const int mrow_ld = lane & 15, kA = (lane >> 4) * 8;
    const int nrow_ld = (lane & 7) + ((lane >> 4) << 3), kB = ((lane >> 3) & 1) * 8;

    // h chunk staging: 64 rows x 16 segs(16B) = 1024 cp16; 4 per thread.
    // u = tid + i*256: b = u>>4, s = u&15. src: b*2048 + c*256 + s*16.
    for (int t = 0; t < T_; t++) {
        const char* hsrc = (const char*)g_hf[t & 3];

        // early z loads
        float zr[2][4];
#pragma unroll
        for (int r = 0; r < 2; r++) {
            const int e = tid + r * 256;
            const size_t zoff = ((size_t)((e >> 3) * T_ + t)) * G4 + j0 + (e & 7);
#pragma unroll
            for (int gg = 0; gg < 4; gg++) zr[r][gg] = g_Z[zoff + (size_t)gg * H_];
        }

        float acc[2][4] = {{0.f,0.f,0.f,0.f},{0.f,0.f,0.f,0.f}};

        // prologue: stage chunks 0 and 1
#pragma unroll
        for (int pc = 0; pc < 2; pc++) {
            volatile int* f = &g_prod[t][pc];
            while (*f < 16) { }
            const uint32_t hb = sb + RS_H + pc * RS_HBUF;
#pragma unroll
            for (int i = 0; i < 4; i++) {
                const int u = tid + i * 256, b = u >> 4, s = u & 15;
                cp16(hb + b * 272 + s * 16, hsrc + b * 2048 + pc * 256 + s * 16);
            }
            cp_commit();
        }

        for (int c = 0; c < 8; c++) {
            if (c + 2 < 8) {
                const int sc = c + 2;
                volatile int* f = &g_prod[t][sc];
                while (*f < 16) { }
                const uint32_t hb = sb + RS_H + (sc & 3) * RS_HBUF;
#pragma unroll
                for (int i = 0; i < 4; i++) {
                    const int u = tid + i * 256, b = u >> 4, s = u & 15;
                    cp16(hb + b * 272 + s * 16, hsrc + b * 2048 + sc * 256 + s * 16);
                }
                cp_commit();
                if (sc == 7 && tid == 0) atomicAdd(&g_cons[t], 1);   // all of h(t) staged
                cp_wait2();
            } else if (c == 6) {
                cp_wait1();
            } else {
                cp_wait0();
            }
            __syncthreads();

            const uint32_t hb = sb + RS_H + (c & 3) * RS_HBUF;
#pragma unroll
            for (int ks = 0; ks < 8; ks++) {
                uint32_t ahr[4], alr[4], bhr[4];
                const uint32_t ra = sb + RS_WHI + (wm * 16 + mrow_ld) * 2064 + (c * 128 + ks * 16 + kA) * 2;
                ldmx4(ahr, ra);
                ldmx4(alr, ra + (RS_WLO - RS_WHI));
                ldmx4(bhr, hb + (wn * 16 + nrow_ld) * 272 + (ks * 16 + kB) * 2);
#pragma unroll
                for (int ti = 0; ti < 2; ti++) {
                    mma_f16(acc[ti], ahr, bhr[ti * 2], bhr[ti * 2 + 1]);
                    mma_f16(acc[ti], alr, bhr[ti * 2], bhr[ti * 2 + 1]);
                }
            }
        }
        __syncthreads();

        // frags -> zsm [row = gate*8+jj][batch]
        {
            const int g = lane >> 2, tq = lane & 3;
#pragma unroll
            for (int ti = 0; ti < 2; ti++) {
                const int col = wn * 16 + ti * 8 + tq * 2;
                zsm[(wm * 16 + g) * 66 + col]         = acc[ti][0];
                zsm[(wm * 16 + g) * 66 + col + 1]     = acc[ti][1];
                zsm[(wm * 16 + g + 8) * 66 + col]     = acc[ti][2];
                zsm[(wm * 16 + g + 8) * 66 + col + 1] = acc[ti][3];
            }
        }
        __syncthreads();

        // WAR guard (2 steps of slack): h(t+1) reuses buffer of h(t-3)
        if (t >= 3) {
            volatile int* f = &g_cons[t - 3];
            while (*f < RNC) { }
        }

        // gates (FMA-pipe math)
        __half* __restrict__ hdst = g_hf[(t + 1) & 3];
#pragma unroll
        for (int r = 0; r < 2; r++) {
            const int e = tid + r * 256;
            const int b = e >> 3, jj = e & 7;
            const float zi = zsm[(0 * 8 + jj) * 66 + b] + zr[r][0];
            const float zf = zsm[(1 * 8 + jj) * 66 + b] + zr[r][1];
            const float zg = zsm[(2 * 8 + jj) * 66 + b] + zr[r][2];
            const float zo = zsm[(3 * 8 + jj) * 66 + b] + zr[r][3];

            const float ef = exp_fast(-zf);
            const float ei = exp_fast(-zi);
            const float eg = exp_fast(-2.f * zg);
            const float eo = exp_fast(-zo);
            const float cc = creg[r] * rcp_fast(1.f + ef)
                           + (1.f - eg) * rcp_fast((1.f + ei) * (1.f + eg));
            const float ec = exp_fast(2.f * cc);
            const float hh = (ec - 1.f) * rcp_fast((1.f + eo) * (ec + 1.f));
            creg[r] = cc;

            const __half hf = __float2half(hh);
            const int hidx = b * H_ + j0 + jj;
            hdst[hidx] = hf;
            g_rf[((size_t)(b * T_ + t)) * H_ + j0 + jj] = hf;
            if (t == T_ - 1) {
                out[OUT_HT_OFF + hidx] = hh;
                out[OUT_CT_OFF + hidx] = cc;
            }
        }
        __threadfence();
        __syncthreads();
        if (tid == 0) atomicAdd(&g_prod[t + 1][my_chunk], 1);
    }
}

// ---------------- heads: 14 dots per row of g_sh ----------------
__global__ __launch_bounds__(256) void heads_kernel(
    const float* __restrict__ w_att_s, const float* __restrict__ w_att_r,
    const float* __restrict__ W_state, const float* __restrict__ W_reward)
{
    const int warp = (blockIdx.x * blockDim.x + threadIdx.x) >> 5;
    const int lane = threadIdx.x & 31;
    if (warp >= BT) return;
    const float* rowp = g_sh + (size_t)warp * H_;

    float4 f[8];
#pragma unroll
    for (int i = 0; i < 8; i++)
        f[i] = *reinterpret_cast<const float4*>(rowp + lane * 32 + i * 4);

    float out[14];
#pragma unroll
    for (int fi = 0; fi < 14; fi++) {
        const float* wv = (fi == 0) ? w_att_s
                        : (fi == 1) ? w_att_r
                        : (fi < 13) ? (W_state + (fi - 2) * H_)
                        : W_reward;
        float s = 0.f;
#pragma unroll
        for (int i = 0; i < 8; i++) {
            const float4 w = *reinterpret_cast<const float4*>(wv + lane * 32 + i * 4);
            s += f[i].x * w.x + f[i].y * w.y + f[i].z * w.z + f[i].w * w.w;
        }
#pragma unroll
        for (int o = 16; o; o >>= 1) s += __shfl_xor_sync(0xffffffffu, s, o);
        out[fi] = s;
    }
    if (lane == 0) {
#pragma unroll
        for (int fi = 0; fi < 14; fi++)
            g_proj[(size_t)warp * 16 + fi] = out[fi];
    }
}

// ---------------- causal prefix-softmax scan ----------------
__global__ void scan_kernel(const float* __restrict__ b_state,
                            const float* __restrict__ b_reward,
                            float* __restrict__ out)
{
    const int b = blockIdx.x;
    const int w = threadIdx.x >> 5, lane = threadIdx.x & 31;
    const float* pbase = g_proj + (size_t)b * T_ * 16;

    if (w == 0) {
        float num = 0.f, den = 0.f, m = -INFINITY;
        const float bs = (lane < F_) ? b_state[lane] : 0.f;
        for (int t = 0; t < T_; t++) {
            const float* p = pbase + t * 16;
            const float l = p[0];
            const float v = (lane < F_) ? p[2 + lane] : 0.f;
            const float nm = fmaxf(m, l);
            const float sc = __expf(m - nm);
            const float e  = __expf(l - nm);
            den = den * sc + e;
            num = num * sc + e * v;
            m = nm;
            if (lane < F_)
                out[OUT_STATE_OFF + (size_t)(b * T_ + t) * F_ + lane] = num / den + bs;
        }
    } else if (w == 1) {
        float num = 0.f, den = 0.f, m = -INFINITY;
        const float br = b_reward[0];
        for (int t = 0; t < T_; t++) {
            const float* p = pbase + t * 16;
            const float l = p[1];
            const float v = p[13];
            const float nm = fmaxf(m, l);
            const float sc = __expf(m - nm);
            const float e  = __expf(l - nm);
            den = den * sc + e;
            num = num * sc + e * v;
            m = nm;
            if (lane == 0)
                out[OUT_REWARD_OFF + b * T_ + t] = num / den + br;
        }
    }
}

// ---------------- launch ----------------
extern "C" void kernel_launch(void* const* d_in, const int* in_sizes, int n_in,
                              void* d_out, int out_size)
{
    const float* x        = (const float*)d_in[0];
    const float* h0       = (const float*)d_in[2];
    const float* c0       = (const float*)d_in[3];
    const float* W_ih     = (const float*)d_in[4];
    const float* W_hh     = (const float*)d_in[5];
    const float* b_ih     = (const float*)d_in[6];
    const float* b_hh     = (const float*)d_in[7];
    const float* W_sh     = (const float*)d_in[8];
    const float* b_sh     = (const float*)d_in[9];
    const float* w_att_s  = (const float*)d_in[10];
    const float* w_att_r  = (const float*)d_in[12];
    const float* W_state  = (const float*)d_in[14];
    const float* b_state  = (const float*)d_in[15];
    const float* W_reward = (const float*)d_in[16];
    const float* b_reward = (const float*)d_in[17];
    float* out = (float*)d_out;

    float *Z, *sh;
    __half *xf, *rf, *wihh, *wihl, *whhh, *whhl, *wshh, *wshl, *hf;
    cudaGetSymbolAddress((void**)&Z,    g_Z);
    cudaGetSymbolAddress((void**)&sh,   g_sh);
    cudaGetSymbolAddress((void**)&xf,   g_xf);
    cudaGetSymbolAddress((void**)&rf,   g_rf);
    cudaGetSymbolAddress((void**)&wihh, g_wih_hi); cudaGetSymbolAddress((void**)&wihl, g_wih_lo);
    cudaGetSymbolAddress((void**)&whhh, g_whh_hi); cudaGetSymbolAddress((void**)&whhl, g_whh_lo);
    cudaGetSymbolAddress((void**)&wshh, g_wsh_hi); cudaGetSymbolAddress((void**)&wshl, g_wsh_lo);
    cudaGetSymbolAddress((void**)&hf,   g_hf);

    cudaFuncSetAttribute(hgemm2, cudaFuncAttributeMaxDynamicSharedMemorySize, GEMM_SMEM);
    cudaFuncSetAttribute(lstm_mma_kernel, cudaFuncAttributeMaxDynamicSharedMemorySize, LSTM_SMEM);

    // conversions + flag init
    cvt16_kernel<<<(BT * I_) / 256, 256>>>(x, xf, BT * I_);
    split16_kernel<<<(G4 * I_) / 256, 256>>>(W_ih, wihh, wihl, G4 * I_);
    split16_kernel<<<(G4 * H_) / 256, 256>>>(W_hh, whhh, whhl, G4 * H_);
    split16_kernel<<<(H_ * H_) / 256, 256>>>(W_sh, wshh, wshl, H_ * H_);
    cvt16_kernel<<<(B_ * H_) / 256, 256>>>(h0, hf, B_ * H_);   // -> g_hf[0]
    init_flags_kernel<<<17, 256>>>();

    // Z = x @ W_ih^T + (b_ih + b_hh)   [32768, 4096], K=256
    hgemm2<<<dim3(G4 / 128, BT / 128), 256, GEMM_SMEM>>>(
        xf, wihh, wihl, b_ih, b_hh, Z, BT, G4, I_);

    // LSTM recurrence
    lstm_mma_kernel<<<RNC, 256, LSTM_SMEM>>>(c0, out);

    // shared = r @ W_sh^T + b_sh   [32768, 1024], K=1024
    hgemm2<<<dim3(H_ / 128, BT / 128), 256, GEMM_SMEM>>>(
        rf, wshh, wshl, b_sh, nullptr, sh, BT, H_, H_);

    // heads + scans
    heads_kernel<<<BT / 8, 256>>>(w_att_s, w_att_r, W_state, W_reward);
    scan_kernel<<<B_, 64>>>(b_state, b_reward, out);
}